// round 11
// baseline (speedup 1.0000x reference)
#include <cuda_runtime.h>
#include <cuda_fp16.h>
#include <cstdint>

// ---------------------------------------------------------------------------
// MoE top-2 projection: out[t] = sum_k w_k * (x[t] @ W[e_k]^T + b[e_k])
// x:[8192,1024] f32, W:[8,1024,1024], b:[8,1024], Wg:[8,1024], bg:[8]
// Route -> per-expert gathered GEMM with mma.sync fp16 (f32 accumulate).
// GEMM: PERSISTENT (148 CTAs, atomic tile claim), CTA tile 128x256, 8 warps
// of 64x64, BK=32, 3-buffer cp.async pipeline, reg fragment double-buffering
// (the R9 mainloop — best measured config; R10's BK=64 regressed).
// ---------------------------------------------------------------------------

#define T_TOKENS 8192
#define DIM      1024
#define OUTD     1024
#define NEXP     8
#define NSM      148

// Scratch (allocation-free rule: __device__ globals)
__device__ __half g_x_h[T_TOKENS * DIM];          // 16 MB
__device__ __half g_w_h[NEXP * OUTD * DIM];       // 16 MB
__device__ int    g_cnt[NEXP + 8];                // [0..7] counts, [8] tile ctr
__device__ int    g_tok[NEXP * T_TOKENS];
__device__ float  g_wt [NEXP * T_TOKENS];

// ---------------------------------------------------------------------------
// Kernel 1 (fused): blocks [0,1024) = gating + x->fp16; blocks [1024,3072) =
// W->fp16 conversion + zero-init of d_out. Independent work, one launch.
// ---------------------------------------------------------------------------
__global__ void __launch_bounds__(256)
fused_prep_gating(const float* __restrict__ x,
                  const float4* __restrict__ W,
                  const float* __restrict__ wg,
                  const float* __restrict__ bg,
                  float4* __restrict__ out4) {
    __shared__ float4 s_wg[NEXP * DIM / 4];  // 32 KB (gating blocks only)
    const int tid = threadIdx.x;

    if (blockIdx.x >= 1024) {
        // ---- prep part: W fp16 convert + out zero ----
        const int gid = (blockIdx.x - 1024) * 256 + tid;
        const int stride = 2048 * 256;        // 524288
        uint4* wh = reinterpret_cast<uint4*>(g_w_h);
        float4 v[4];
#pragma unroll
        for (int i = 0; i < 2; i++) {
            int j = gid + i * stride;
            v[2 * i]     = W[2 * j];
            v[2 * i + 1] = W[2 * j + 1];
        }
#pragma unroll
        for (int i = 0; i < 2; i++) {
            int j = gid + i * stride;
            __half2 h0 = __float22half2_rn(make_float2(v[2*i].x,   v[2*i].y));
            __half2 h1 = __float22half2_rn(make_float2(v[2*i].z,   v[2*i].w));
            __half2 h2 = __float22half2_rn(make_float2(v[2*i+1].x, v[2*i+1].y));
            __half2 h3 = __float22half2_rn(make_float2(v[2*i+1].z, v[2*i+1].w));
            uint4 p;
            p.x = *(uint32_t*)&h0; p.y = *(uint32_t*)&h1;
            p.z = *(uint32_t*)&h2; p.w = *(uint32_t*)&h3;
            wh[j] = p;
        }
        float4 z = make_float4(0.f, 0.f, 0.f, 0.f);
#pragma unroll
        for (int i = 0; i < 4; i++) out4[gid + i * stride] = z;
        return;
    }

    // ---- gating part: exact fp32 gate, top-2 route, x -> fp16 ----
    const float4* wg4 = (const float4*)wg;
    for (int i = tid; i < NEXP * DIM / 4; i += 256) s_wg[i] = wg4[i];
    __syncthreads();

    const int lid = tid & 31;
    const int t = blockIdx.x * 8 + (tid >> 5);
    const float4* xr = (const float4*)(x + (size_t)t * DIM);
    uint2* xo = (uint2*)(g_x_h + (size_t)t * DIM);

    float acc[NEXP];
#pragma unroll
    for (int e = 0; e < NEXP; e++) acc[e] = 0.f;

#pragma unroll
    for (int j = 0; j < 8; j++) {
        int c = lid + j * 32;
        float4 v = xr[c];
        __half2 h0 = __float22half2_rn(make_float2(v.x, v.y));
        __half2 h1 = __float22half2_rn(make_float2(v.z, v.w));
        uint2 p; p.x = *(uint32_t*)&h0; p.y = *(uint32_t*)&h1;
        xo[c] = p;
#pragma unroll
        for (int e = 0; e < NEXP; e++) {
            float4 w = s_wg[e * 256 + c];
            acc[e] += v.x * w.x + v.y * w.y + v.z * w.z + v.w * w.w;
        }
    }
#pragma unroll
    for (int e = 0; e < NEXP; e++) {
#pragma unroll
        for (int o = 16; o > 0; o >>= 1)
            acc[e] += __shfl_xor_sync(0xFFFFFFFFu, acc[e], o);
    }

    if (lid == 0) {
        float l[NEXP];
#pragma unroll
        for (int e = 0; e < NEXP; e++) l[e] = acc[e] + bg[e];  // TEMP = 1
        int i0 = 0;
#pragma unroll
        for (int e = 1; e < NEXP; e++) if (l[e] > l[i0]) i0 = e;
        int i1 = -1;
#pragma unroll
        for (int e = 0; e < NEXP; e++) {
            if (e == i0) continue;
            if (i1 < 0 || l[e] > l[i1]) i1 = e;
        }
        float mx = l[0];
#pragma unroll
        for (int e = 1; e < NEXP; e++) mx = fmaxf(mx, l[e]);
        float s = 0.f;
#pragma unroll
        for (int e = 0; e < NEXP; e++) s += expf(l[e] - mx);
        float inv = 1.f / s;
        float w0 = expf(l[i0] - mx) * inv;
        float w1 = expf(l[i1] - mx) * inv;
        int p0 = atomicAdd(&g_cnt[i0], 1);
        g_tok[i0 * T_TOKENS + p0] = t; g_wt[i0 * T_TOKENS + p0] = w0;
        int p1 = atomicAdd(&g_cnt[i1], 1);
        g_tok[i1 * T_TOKENS + p1] = t; g_wt[i1 * T_TOKENS + p1] = w1;
    }
}

// ---------------------------------------------------------------------------
// sm_100-portable helpers
// ---------------------------------------------------------------------------
__device__ __forceinline__ uint32_t smem_u32(const void* p) {
    uint32_t a;
    asm("{ .reg .u64 t; cvta.to.shared.u64 t, %1; cvt.u32.u64 %0, t; }"
        : "=r"(a) : "l"(p));
    return a;
}
__device__ __forceinline__ void cp16(uint32_t dst, const void* src, uint32_t sz) {
    asm volatile("cp.async.cg.shared.global [%0], [%1], 16, %2;"
                 :: "r"(dst), "l"(src), "r"(sz) : "memory");
}
__device__ __forceinline__ void ldm_x4(uint32_t* r, uint32_t addr) {
    asm volatile("ldmatrix.sync.aligned.m8n8.x4.shared.b16 {%0,%1,%2,%3}, [%4];"
                 : "=r"(r[0]), "=r"(r[1]), "=r"(r[2]), "=r"(r[3]) : "r"(addr));
}
__device__ __forceinline__ void mma_f16(float* c, const uint32_t* a,
                                        uint32_t b0, uint32_t b1) {
    asm volatile(
        "mma.sync.aligned.m16n8k16.row.col.f32.f16.f16.f32 "
        "{%0,%1,%2,%3}, {%4,%5,%6,%7}, {%8,%9}, {%0,%1,%2,%3};"
        : "+f"(c[0]), "+f"(c[1]), "+f"(c[2]), "+f"(c[3])
        : "r"(a[0]), "r"(a[1]), "r"(a[2]), "r"(a[3]), "r"(b0), "r"(b1));
}
__device__ __forceinline__ void red2(float* p, float a, float b) {
    asm volatile("red.relaxed.gpu.global.add.v2.f32 [%0], {%1, %2};"
                 :: "l"(p), "f"(a), "f"(b) : "memory");
}

// ---------------------------------------------------------------------------
// Kernel 2: PERSISTENT routed GEMM. grid = 148 CTAs, 1/SM.
// Valid tiles enumerated expert-major: per expert e, ceil(cnt/128) m-tiles
// x 4 n-tiles (nt innermost -> consecutive claims share gathered A in L2).
// CTAs claim tiles via atomicAdd on g_cnt[8]. Per tile: R9 mainloop —
// 128x256x1024, BK=32, 8 warps of 64x64, pitch 80 B, 3 smem buffers,
// reg fragment double-buffer across kk and stage boundary.
// SMEM: 3*10240 + 3*20480 + 1024 = 93184 B.
// ---------------------------------------------------------------------------
#define PITCH_B  80       // bytes per smem row
#define STG_A    10240    // 128 rows * 80 B
#define STG_B    20480    // 256 rows * 80 B

__global__ void __launch_bounds__(256, 1)
moe_gemm_persistent(const float* __restrict__ bias, float* __restrict__ out) {
    extern __shared__ char smem[];
    char* sA = smem;
    char* sB = smem + 3 * STG_A;
    int*   sTok = (int*)(smem + 3 * STG_A + 3 * STG_B);
    float* sWt  = (float*)(smem + 3 * STG_A + 3 * STG_B + 512);
    __shared__ int s_tile;

    const int tid  = threadIdx.x;
    const int wid  = tid >> 5;
    const int lane = tid & 31;
    const int wm   = wid & 1;   // 2 m-blocks of 64
    const int wn   = wid >> 1;  // 4 n-blocks of 64

    // Tile enumeration prefix (counts are final before this kernel runs).
    int pre[NEXP + 1];
    pre[0] = 0;
#pragma unroll
    for (int e = 0; e < NEXP; e++) {
        int c = g_cnt[e];
        pre[e + 1] = pre[e] + ((c + 127) >> 7) * 4;
    }
    const int total_tiles = pre[NEXP];

    const uint32_t aBase = smem_u32(sA);
    const uint32_t bBase = smem_u32(sB);
    const uint32_t aA0 = aBase + (uint32_t)((wm * 64 + (lane & 15)) * PITCH_B)
                               + (uint32_t)((lane >> 4) * 16);
    const uint32_t bA0 = bBase + (uint32_t)((wn * 64 + ((lane >> 4) << 3) + (lane & 7)) * PITCH_B)
                               + (uint32_t)(((lane >> 3) & 1) * 16);

    for (;;) {
        if (tid == 0) s_tile = atomicAdd(&g_cnt[NEXP], 1);
        __syncthreads();   // publishes s_tile; prior epilogue reads of sTok done
        const int v = s_tile;
        if (v >= total_tiles) return;

        // v -> (e, mt, nt); nt innermost.
        int e = 0;
#pragma unroll
        for (int k = 1; k < NEXP; k++) if (v >= pre[k]) e = k;
        const int rem = v - pre[e];
        const int mt = rem >> 2;
        const int nt = rem & 3;
        const int cnt = g_cnt[e];

        if (tid < 128) {
            int idx = mt * 128 + tid;
            int tok = -1; float w = 0.f;
            if (idx < cnt) { tok = g_tok[e * T_TOKENS + idx]; w = g_wt[e * T_TOKENS + idx]; }
            sTok[tid] = tok; sWt[tid] = w;
        }
        __syncthreads();

        // --- cp.async slots: A 512 chunks (2/thr), B 1024 chunks (4/thr) ---
        const __half* aSrc[2];
        uint32_t      aSz[2];
        uint32_t      aOff[2];
        const __half* bSrc[4];
        uint32_t      bOff[4];
        const __half* wrow = g_w_h + ((size_t)(e * OUTD + nt * 256)) * DIM;
#pragma unroll
        for (int i = 0; i < 2; i++) {
            int f = tid + i * 256;
            int r = f >> 2, q = f & 3;   // A row, 16B chunk
            int tok = sTok[r];
            aSrc[i] = (tok >= 0 ? g_x_h + (size_t)tok * DIM : g_x_h) + q * 8;
            aSz[i]  = (tok >= 0) ? 16u : 0u;   // zfill padding rows
            aOff[i] = (uint32_t)(r * PITCH_B + q * 16);
        }
#pragma unroll
        for (int i = 0; i < 4; i++) {
            int f = tid + i * 256;
            int r = f >> 2, q = f & 3;   // B row (0..255), 16B chunk
            bSrc[i] = wrow + (size_t)r * DIM + q * 8;
            bOff[i] = (uint32_t)(r * PITCH_B + q * 16);
        }

        auto prefetch = [&](int s, int buf) {
            uint32_t sta = (uint32_t)buf * STG_A;
            uint32_t stb = (uint32_t)buf * STG_B;
            int ko = s * 32;  // half offset along K
#pragma unroll
            for (int i = 0; i < 2; i++) cp16(aBase + sta + aOff[i], aSrc[i] + ko, aSz[i]);
#pragma unroll
            for (int i = 0; i < 4; i++) cp16(bBase + stb + bOff[i], bSrc[i] + ko, 16u);
        };

        prefetch(0, 0);
        asm volatile("cp.async.commit_group;" ::: "memory");
        prefetch(1, 1);
        asm volatile("cp.async.commit_group;" ::: "memory");

        float c[4][8][4];
#pragma unroll
        for (int mf = 0; mf < 4; mf++)
#pragma unroll
            for (int nf = 0; nf < 8; nf++)
#pragma unroll
                for (int j = 0; j < 4; j++) c[mf][nf][j] = 0.f;

        uint32_t af[2][4][4];   // [kk-slot][mf][reg]
        uint32_t bf[2][4][4];   // [kk-slot][pr][reg]

        auto ldsFrag = [&](int slot, uint32_t sa, uint32_t sb, int kk) {
#pragma unroll
            for (int mf = 0; mf < 4; mf++)
                ldm_x4(af[slot][mf], sa + (uint32_t)(mf * 16 * PITCH_B) + (uint32_t)(kk * 32));
#pragma unroll
            for (int pr = 0; pr < 4; pr++)
                ldm_x4(bf[slot][pr], sb + (uint32_t)(pr * 16 * PITCH_B) + (uint32_t)(kk * 32));
        };
        auto mmaBlk = [&](int slot) {
#pragma unroll
            for (int mf = 0; mf < 4; mf++)
#pragma unroll
                for (int nf = 0; nf < 8; nf++)
                    mma_f16(c[mf][nf], af[slot][mf],
                            bf[slot][nf >> 1][(nf & 1) * 2], bf[slot][nf >> 1][(nf & 1) * 2 + 1]);
        };

        // ---- peeled stage 0 ----
        asm volatile("cp.async.wait_group 1;" ::: "memory");
        __syncthreads();
        prefetch(2, 2);
        asm volatile("cp.async.commit_group;" ::: "memory");
        ldsFrag(0, aA0, bA0, 0);
        ldsFrag(1, aA0, bA0, 1);
        mmaBlk(0);

        for (int s = 1; s < 32; s++) {
            asm volatile("cp.async.wait_group 1;" ::: "memory");
            __syncthreads();  // stage s smem ready; buffer (s-1)%3 fully read
            if (s + 2 < 32) prefetch(s + 2, (s + 2) % 3);
            asm volatile("cp.async.commit_group;" ::: "memory");

            const uint32_t off = (uint32_t)(s % 3);
            const uint32_t sa = aA0 + off * STG_A;
            const uint32_t sb = bA0 + off * STG_B;
            ldsFrag(0, sa, sb, 0);   // stage s, kk0
            mmaBlk(1);               // stage s-1, kk1 (regs only)
            ldsFrag(1, sa, sb, 1);   // stage s, kk1
            mmaBlk(0);               // stage s, kk0
        }
        mmaBlk(1);  // final stage kk1

        // --- epilogue: bias + gate-weight scale + global reduction ---
        const int nbase = nt * 256;
        const float* bptr = bias + e * OUTD + nbase;
#pragma unroll
        for (int mf = 0; mf < 4; mf++) {
            int m0 = wm * 64 + mf * 16 + (lane >> 2);
            int m1 = m0 + 8;
            int t0 = sTok[m0], t1 = sTok[m1];
            float w0 = sWt[m0], w1 = sWt[m1];
#pragma unroll
            for (int nf = 0; nf < 8; nf++) {
                int col = wn * 64 + nf * 8 + 2 * (lane & 3);
                float2 bb = *(const float2*)(bptr + col);
                if (t0 >= 0) {
                    red2(out + (size_t)t0 * OUTD + nbase + col,
                         w0 * (c[mf][nf][0] + bb.x), w0 * (c[mf][nf][1] + bb.y));
                }
                if (t1 >= 0) {
                    red2(out + (size_t)t1 * OUTD + nbase + col,
                         w1 * (c[mf][nf][2] + bb.x), w1 * (c[mf][nf][3] + bb.y));
                }
            }
        }
        // loop-top __syncthreads() protects sTok/sWt reuse
    }
}

// ---------------------------------------------------------------------------
extern "C" void kernel_launch(void* const* d_in, const int* in_sizes, int n_in,
                              void* d_out, int out_size) {
    const float* x  = (const float*)d_in[0];   // [4,2048,1024]
    const float* W  = (const float*)d_in[1];   // [8,1024,1024]
    const float* b  = (const float*)d_in[2];   // [8,1024]
    const float* Wg = (const float*)d_in[3];   // [8,1024]
    const float* bg = (const float*)d_in[4];   // [8]
    float* out = (float*)d_out;                // [4,2048,1024] f32

    static void* cnt_addr = nullptr;
    if (!cnt_addr) {
        cudaGetSymbolAddress(&cnt_addr, g_cnt);
        cudaFuncSetAttribute(moe_gemm_persistent,
                             cudaFuncAttributeMaxDynamicSharedMemorySize, 93184);
    }

    cudaMemsetAsync(cnt_addr, 0, (NEXP + 8) * sizeof(int));
    fused_prep_gating<<<3072, 256>>>(x, (const float4*)W, Wg, bg, (float4*)out);
    moe_gemm_persistent<<<NSM, 256, 93184>>>(b, out);
}

// round 12
// speedup vs baseline: 1.0373x; 1.0373x over previous
#include <cuda_runtime.h>
#include <cuda_fp16.h>
#include <cstdint>

// ---------------------------------------------------------------------------
// MoE top-2 projection: out[t] = sum_k w_k * (x[t] @ W[e_k]^T + b[e_k])
// x:[8192,1024] f32, W:[8,1024,1024], b:[8,1024], Wg:[8,1024], bg:[8]
// Route -> per-expert gathered GEMM with mma.sync fp16 (f32 accumulate).
// R9 config (best measured): grid (4,64,8), CTA 128x256, 8 warps of 64x64,
// BK=32, reg fragment double-buffering. Deltas this round: d_out zeroed by
// cudaMemsetAsync (not the prep kernel); 4 smem buffers with lookahead 3.
// ---------------------------------------------------------------------------

#define T_TOKENS 8192
#define DIM      1024
#define OUTD     1024
#define NEXP     8

// Scratch (allocation-free rule: __device__ globals)
__device__ __half g_x_h[T_TOKENS * DIM];          // 16 MB
__device__ __half g_w_h[NEXP * OUTD * DIM];       // 16 MB
__device__ int    g_cnt[NEXP];                    // zeroed via cudaMemsetAsync
__device__ int    g_tok[NEXP * T_TOKENS];
__device__ float  g_wt [NEXP * T_TOKENS];

// ---------------------------------------------------------------------------
// Kernel 1 (fused): blocks [0,1024) = gating + x->fp16; blocks [1024,3072) =
// W->fp16 conversion. (d_out zeroing moved to cudaMemsetAsync.)
// ---------------------------------------------------------------------------
__global__ void __launch_bounds__(256)
fused_prep_gating(const float* __restrict__ x,
                  const float4* __restrict__ W,
                  const float* __restrict__ wg,
                  const float* __restrict__ bg) {
    __shared__ float4 s_wg[NEXP * DIM / 4];  // 32 KB (gating blocks only)
    const int tid = threadIdx.x;

    if (blockIdx.x >= 1024) {
        // ---- prep part: W fp16 convert ----
        const int gid = (blockIdx.x - 1024) * 256 + tid;
        const int stride = 2048 * 256;        // 524288
        uint4* wh = reinterpret_cast<uint4*>(g_w_h);
        float4 v[4];
#pragma unroll
        for (int i = 0; i < 2; i++) {
            int j = gid + i * stride;
            v[2 * i]     = W[2 * j];
            v[2 * i + 1] = W[2 * j + 1];
        }
#pragma unroll
        for (int i = 0; i < 2; i++) {
            int j = gid + i * stride;
            __half2 h0 = __float22half2_rn(make_float2(v[2*i].x,   v[2*i].y));
            __half2 h1 = __float22half2_rn(make_float2(v[2*i].z,   v[2*i].w));
            __half2 h2 = __float22half2_rn(make_float2(v[2*i+1].x, v[2*i+1].y));
            __half2 h3 = __float22half2_rn(make_float2(v[2*i+1].z, v[2*i+1].w));
            uint4 p;
            p.x = *(uint32_t*)&h0; p.y = *(uint32_t*)&h1;
            p.z = *(uint32_t*)&h2; p.w = *(uint32_t*)&h3;
            wh[j] = p;
        }
        return;
    }

    // ---- gating part: exact fp32 gate, top-2 route, x -> fp16 ----
    const float4* wg4 = (const float4*)wg;
    for (int i = tid; i < NEXP * DIM / 4; i += 256) s_wg[i] = wg4[i];
    __syncthreads();

    const int lid = tid & 31;
    const int t = blockIdx.x * 8 + (tid >> 5);
    const float4* xr = (const float4*)(x + (size_t)t * DIM);
    uint2* xo = (uint2*)(g_x_h + (size_t)t * DIM);

    float acc[NEXP];
#pragma unroll
    for (int e = 0; e < NEXP; e++) acc[e] = 0.f;

#pragma unroll
    for (int j = 0; j < 8; j++) {
        int c = lid + j * 32;
        float4 v = xr[c];
        __half2 h0 = __float22half2_rn(make_float2(v.x, v.y));
        __half2 h1 = __float22half2_rn(make_float2(v.z, v.w));
        uint2 p; p.x = *(uint32_t*)&h0; p.y = *(uint32_t*)&h1;
        xo[c] = p;
#pragma unroll
        for (int e = 0; e < NEXP; e++) {
            float4 w = s_wg[e * 256 + c];
            acc[e] += v.x * w.x + v.y * w.y + v.z * w.z + v.w * w.w;
        }
    }
#pragma unroll
    for (int e = 0; e < NEXP; e++) {
#pragma unroll
        for (int o = 16; o > 0; o >>= 1)
            acc[e] += __shfl_xor_sync(0xFFFFFFFFu, acc[e], o);
    }

    if (lid == 0) {
        float l[NEXP];
#pragma unroll
        for (int e = 0; e < NEXP; e++) l[e] = acc[e] + bg[e];  // TEMP = 1
        int i0 = 0;
#pragma unroll
        for (int e = 1; e < NEXP; e++) if (l[e] > l[i0]) i0 = e;
        int i1 = -1;
#pragma unroll
        for (int e = 0; e < NEXP; e++) {
            if (e == i0) continue;
            if (i1 < 0 || l[e] > l[i1]) i1 = e;
        }
        float mx = l[0];
#pragma unroll
        for (int e = 1; e < NEXP; e++) mx = fmaxf(mx, l[e]);
        float s = 0.f;
#pragma unroll
        for (int e = 0; e < NEXP; e++) s += expf(l[e] - mx);
        float inv = 1.f / s;
        float w0 = expf(l[i0] - mx) * inv;
        float w1 = expf(l[i1] - mx) * inv;
        int p0 = atomicAdd(&g_cnt[i0], 1);
        g_tok[i0 * T_TOKENS + p0] = t; g_wt[i0 * T_TOKENS + p0] = w0;
        int p1 = atomicAdd(&g_cnt[i1], 1);
        g_tok[i1 * T_TOKENS + p1] = t; g_wt[i1 * T_TOKENS + p1] = w1;
    }
}

// ---------------------------------------------------------------------------
// sm_100-portable helpers
// ---------------------------------------------------------------------------
__device__ __forceinline__ uint32_t smem_u32(const void* p) {
    uint32_t a;
    asm("{ .reg .u64 t; cvta.to.shared.u64 t, %1; cvt.u32.u64 %0, t; }"
        : "=r"(a) : "l"(p));
    return a;
}
__device__ __forceinline__ void cp16(uint32_t dst, const void* src, uint32_t sz) {
    asm volatile("cp.async.cg.shared.global [%0], [%1], 16, %2;"
                 :: "r"(dst), "l"(src), "r"(sz) : "memory");
}
__device__ __forceinline__ void ldm_x4(uint32_t* r, uint32_t addr) {
    asm volatile("ldmatrix.sync.aligned.m8n8.x4.shared.b16 {%0,%1,%2,%3}, [%4];"
                 : "=r"(r[0]), "=r"(r[1]), "=r"(r[2]), "=r"(r[3]) : "r"(addr));
}
__device__ __forceinline__ void mma_f16(float* c, const uint32_t* a,
                                        uint32_t b0, uint32_t b1) {
    asm volatile(
        "mma.sync.aligned.m16n8k16.row.col.f32.f16.f16.f32 "
        "{%0,%1,%2,%3}, {%4,%5,%6,%7}, {%8,%9}, {%0,%1,%2,%3};"
        : "+f"(c[0]), "+f"(c[1]), "+f"(c[2]), "+f"(c[3])
        : "r"(a[0]), "r"(a[1]), "r"(a[2]), "r"(a[3]), "r"(b0), "r"(b1));
}
__device__ __forceinline__ void red2(float* p, float a, float b) {
    asm volatile("red.relaxed.gpu.global.add.v2.f32 [%0], {%1, %2};"
                 :: "l"(p), "f"(a), "f"(b) : "memory");
}

// ---------------------------------------------------------------------------
// Kernel 2: routed GEMM. grid = (4 N-tiles, 64 M-tiles, 8 experts).
// 128x256x1024 per CTA; BK=32; 8 warps of 64x64; pitch 80 B (conflict-free
// ldmatrix); reg fragment double-buffer across kk and stage boundary.
// 4 smem buffers, lookahead 3, wait_group 2, one bar per stage:
//   wait_group(2) -> bar -> prefetch(s+3 into buffer freed by s-1) -> commit
//   -> ldsm kk0(s); mma kk1(s-1); ldsm kk1(s); mma kk0(s)
// SMEM: 4*10240 + 4*20480 + 1024 = 123904 B (1 CTA/SM; regs cap at 1 anyway).
// ---------------------------------------------------------------------------
#define PITCH_B  80       // bytes per smem row
#define STG_A    10240    // 128 rows * 80 B
#define STG_B    20480    // 256 rows * 80 B
#define NBUF     4

__global__ void __launch_bounds__(256, 1)
moe_gemm_kernel(const float* __restrict__ bias, float* __restrict__ out) {
    extern __shared__ char smem[];
    const int e  = blockIdx.z;
    const int mt = blockIdx.y;
    const int nt = blockIdx.x;
    const int cnt = g_cnt[e];
    if (mt * 128 >= cnt) return;

    const int tid  = threadIdx.x;
    const int wid  = tid >> 5;
    const int lane = tid & 31;
    const int wm   = wid & 1;   // 2 m-blocks of 64
    const int wn   = wid >> 1;  // 4 n-blocks of 64

    char* sA = smem;
    char* sB = smem + NBUF * STG_A;
    int*   sTok = (int*)(smem + NBUF * (STG_A + STG_B));
    float* sWt  = (float*)(smem + NBUF * (STG_A + STG_B) + 512);

    if (tid < 128) {
        int idx = mt * 128 + tid;
        int tok = -1; float w = 0.f;
        if (idx < cnt) { tok = g_tok[e * T_TOKENS + idx]; w = g_wt[e * T_TOKENS + idx]; }
        sTok[tid] = tok; sWt[tid] = w;
    }
    __syncthreads();

    // --- cp.async slots. A: 512 chunks (2/thread); B: 1024 chunks (4/thread)
    const __half* aSrc[2];
    uint32_t      aSz[2];
    uint32_t      aOff[2];
    const __half* bSrc[4];
    uint32_t      bOff[4];
    const __half* wrow = g_w_h + ((size_t)(e * OUTD + nt * 256)) * DIM;
#pragma unroll
    for (int i = 0; i < 2; i++) {
        int f = tid + i * 256;
        int r = f >> 2, q = f & 3;   // A row, 16B chunk
        int tok = sTok[r];
        aSrc[i] = (tok >= 0 ? g_x_h + (size_t)tok * DIM : g_x_h) + q * 8;
        aSz[i]  = (tok >= 0) ? 16u : 0u;   // zfill padding rows
        aOff[i] = (uint32_t)(r * PITCH_B + q * 16);
    }
#pragma unroll
    for (int i = 0; i < 4; i++) {
        int f = tid + i * 256;
        int r = f >> 2, q = f & 3;   // B row (0..255), 16B chunk
        bSrc[i] = wrow + (size_t)r * DIM + q * 8;
        bOff[i] = (uint32_t)(r * PITCH_B + q * 16);
    }

    const uint32_t aBase = smem_u32(sA);
    const uint32_t bBase = smem_u32(sB);

    auto prefetch = [&](int s, int buf) {
        uint32_t sta = (uint32_t)buf * STG_A;
        uint32_t stb = (uint32_t)buf * STG_B;
        int ko = s * 32;  // half offset along K
#pragma unroll
        for (int i = 0; i < 2; i++) cp16(aBase + sta + aOff[i], aSrc[i] + ko, aSz[i]);
#pragma unroll
        for (int i = 0; i < 4; i++) cp16(bBase + stb + bOff[i], bSrc[i] + ko, 16u);
    };

    prefetch(0, 0);
    asm volatile("cp.async.commit_group;" ::: "memory");
    prefetch(1, 1);
    asm volatile("cp.async.commit_group;" ::: "memory");
    prefetch(2, 2);
    asm volatile("cp.async.commit_group;" ::: "memory");

    // ldmatrix fragment base addresses (per-buffer offsets added in loop)
    const uint32_t aA0 = aBase + (uint32_t)((wm * 64 + (lane & 15)) * PITCH_B)
                               + (uint32_t)((lane >> 4) * 16);
    const uint32_t bA0 = bBase + (uint32_t)((wn * 64 + ((lane >> 4) << 3) + (lane & 7)) * PITCH_B)
                               + (uint32_t)(((lane >> 3) & 1) * 16);

    float c[4][8][4];
#pragma unroll
    for (int mf = 0; mf < 4; mf++)
#pragma unroll
        for (int nf = 0; nf < 8; nf++)
#pragma unroll
            for (int j = 0; j < 4; j++) c[mf][nf][j] = 0.f;

    uint32_t af[2][4][4];   // [kk-slot][mf][reg]
    uint32_t bf[2][4][4];   // [kk-slot][pr][reg]

    auto ldsFrag = [&](int slot, uint32_t sa, uint32_t sb, int kk) {
#pragma unroll
        for (int mf = 0; mf < 4; mf++)
            ldm_x4(af[slot][mf], sa + (uint32_t)(mf * 16 * PITCH_B) + (uint32_t)(kk * 32));
#pragma unroll
        for (int pr = 0; pr < 4; pr++)
            ldm_x4(bf[slot][pr], sb + (uint32_t)(pr * 16 * PITCH_B) + (uint32_t)(kk * 32));
    };
    auto mmaBlk = [&](int slot) {
#pragma unroll
        for (int mf = 0; mf < 4; mf++)
#pragma unroll
            for (int nf = 0; nf < 8; nf++)
                mma_f16(c[mf][nf], af[slot][mf],
                        bf[slot][nf >> 1][(nf & 1) * 2], bf[slot][nf >> 1][(nf & 1) * 2 + 1]);
    };

    // ---- peeled stage 0 ----
    asm volatile("cp.async.wait_group 2;" ::: "memory");
    __syncthreads();
    prefetch(3, 3);
    asm volatile("cp.async.commit_group;" ::: "memory");
    ldsFrag(0, aA0, bA0, 0);
    ldsFrag(1, aA0, bA0, 1);
    mmaBlk(0);

    for (int s = 1; s < 32; s++) {
        asm volatile("cp.async.wait_group 2;" ::: "memory");  // stage s landed
        __syncthreads();  // stage s visible; buffer (s-1)%4 fully read
        if (s + 3 < 32) prefetch(s + 3, (s + 3) % NBUF);
        asm volatile("cp.async.commit_group;" ::: "memory");

        const uint32_t off = (uint32_t)(s % NBUF);
        const uint32_t sa = aA0 + off * STG_A;
        const uint32_t sb = bA0 + off * STG_B;
        ldsFrag(0, sa, sb, 0);   // stage s, kk0
        mmaBlk(1);               // stage s-1, kk1 (regs only)
        ldsFrag(1, sa, sb, 1);   // stage s, kk1
        mmaBlk(0);               // stage s, kk0
    }
    mmaBlk(1);  // final stage kk1

    // --- epilogue: bias + gate-weight scale + vectorized global reduction ---
    const int nbase = nt * 256;
    const float* bptr = bias + e * OUTD + nbase;
#pragma unroll
    for (int mf = 0; mf < 4; mf++) {
        int m0 = wm * 64 + mf * 16 + (lane >> 2);
        int m1 = m0 + 8;
        int t0 = sTok[m0], t1 = sTok[m1];
        float w0 = sWt[m0], w1 = sWt[m1];
#pragma unroll
        for (int nf = 0; nf < 8; nf++) {
            int col = wn * 64 + nf * 8 + 2 * (lane & 3);
            float2 bb = *(const float2*)(bptr + col);
            if (t0 >= 0) {
                red2(out + (size_t)t0 * OUTD + nbase + col,
                     w0 * (c[mf][nf][0] + bb.x), w0 * (c[mf][nf][1] + bb.y));
            }
            if (t1 >= 0) {
                red2(out + (size_t)t1 * OUTD + nbase + col,
                     w1 * (c[mf][nf][2] + bb.x), w1 * (c[mf][nf][3] + bb.y));
            }
        }
    }
}

// ---------------------------------------------------------------------------
extern "C" void kernel_launch(void* const* d_in, const int* in_sizes, int n_in,
                              void* d_out, int out_size) {
    const float* x  = (const float*)d_in[0];   // [4,2048,1024]
    const float* W  = (const float*)d_in[1];   // [8,1024,1024]
    const float* b  = (const float*)d_in[2];   // [8,1024]
    const float* Wg = (const float*)d_in[3];   // [8,1024]
    const float* bg = (const float*)d_in[4];   // [8]
    float* out = (float*)d_out;                // [4,2048,1024] f32

    static void* cnt_addr = nullptr;
    if (!cnt_addr) {
        cudaGetSymbolAddress(&cnt_addr, g_cnt);
        cudaFuncSetAttribute(moe_gemm_kernel,
                             cudaFuncAttributeMaxDynamicSharedMemorySize, 123904);
    }

    cudaMemsetAsync(cnt_addr, 0, NEXP * sizeof(int));
    cudaMemsetAsync(d_out, 0, (size_t)out_size * sizeof(float));
    fused_prep_gating<<<3072, 256>>>(x, (const float4*)W, Wg, bg);
    dim3 grid(4, 64, 8);
    moe_gemm_kernel<<<grid, 256, 123904>>>(b, out);
}

// round 13
// speedup vs baseline: 1.1150x; 1.0749x over previous
#include <cuda_runtime.h>
#include <cuda_fp16.h>
#include <cstdint>

// ---------------------------------------------------------------------------
// MoE top-2 projection: out[t] = sum_k w_k * (x[t] @ W[e_k]^T + b[e_k])
// x:[8192,1024] f32, W:[8,1024,1024], b:[8,1024], Wg:[8,1024], bg:[8]
// Route -> per-expert gathered GEMM with mma.sync fp16 (f32 accumulate).
// R9 structure (best measured) with ONE delta: prefetch issued BEFORE
// cp.async.wait_group (fills the wait stall; needs NBUF=4 for safety).
// ---------------------------------------------------------------------------

#define T_TOKENS 8192
#define DIM      1024
#define OUTD     1024
#define NEXP     8

// Scratch (allocation-free rule: __device__ globals)
__device__ __half g_x_h[T_TOKENS * DIM];          // 16 MB
__device__ __half g_w_h[NEXP * OUTD * DIM];       // 16 MB
__device__ int    g_cnt[NEXP];                    // zeroed via cudaMemsetAsync
__device__ int    g_tok[NEXP * T_TOKENS];
__device__ float  g_wt [NEXP * T_TOKENS];

// ---------------------------------------------------------------------------
// Kernel 1 (fused): blocks [0,1024) = gating + x->fp16; blocks [1024,3072) =
// W->fp16 conversion + zero-init of d_out (fused zeroing was faster than a
// separate memset — measured R9 vs R12). Independent work, one launch.
// ---------------------------------------------------------------------------
__global__ void __launch_bounds__(256)
fused_prep_gating(const float* __restrict__ x,
                  const float4* __restrict__ W,
                  const float* __restrict__ wg,
                  const float* __restrict__ bg,
                  float4* __restrict__ out4) {
    __shared__ float4 s_wg[NEXP * DIM / 4];  // 32 KB (gating blocks only)
    const int tid = threadIdx.x;

    if (blockIdx.x >= 1024) {
        // ---- prep part: W fp16 convert + out zero ----
        const int gid = (blockIdx.x - 1024) * 256 + tid;
        const int stride = 2048 * 256;        // 524288
        uint4* wh = reinterpret_cast<uint4*>(g_w_h);
        float4 v[4];
#pragma unroll
        for (int i = 0; i < 2; i++) {
            int j = gid + i * stride;
            v[2 * i]     = W[2 * j];
            v[2 * i + 1] = W[2 * j + 1];
        }
#pragma unroll
        for (int i = 0; i < 2; i++) {
            int j = gid + i * stride;
            __half2 h0 = __float22half2_rn(make_float2(v[2*i].x,   v[2*i].y));
            __half2 h1 = __float22half2_rn(make_float2(v[2*i].z,   v[2*i].w));
            __half2 h2 = __float22half2_rn(make_float2(v[2*i+1].x, v[2*i+1].y));
            __half2 h3 = __float22half2_rn(make_float2(v[2*i+1].z, v[2*i+1].w));
            uint4 p;
            p.x = *(uint32_t*)&h0; p.y = *(uint32_t*)&h1;
            p.z = *(uint32_t*)&h2; p.w = *(uint32_t*)&h3;
            wh[j] = p;
        }
        float4 z = make_float4(0.f, 0.f, 0.f, 0.f);
#pragma unroll
        for (int i = 0; i < 4; i++) out4[gid + i * stride] = z;
        return;
    }

    // ---- gating part: exact fp32 gate, top-2 route, x -> fp16 ----
    const float4* wg4 = (const float4*)wg;
    for (int i = tid; i < NEXP * DIM / 4; i += 256) s_wg[i] = wg4[i];
    __syncthreads();

    const int lid = tid & 31;
    const int t = blockIdx.x * 8 + (tid >> 5);
    const float4* xr = (const float4*)(x + (size_t)t * DIM);
    uint2* xo = (uint2*)(g_x_h + (size_t)t * DIM);

    float acc[NEXP];
#pragma unroll
    for (int e = 0; e < NEXP; e++) acc[e] = 0.f;

#pragma unroll
    for (int j = 0; j < 8; j++) {
        int c = lid + j * 32;
        float4 v = xr[c];
        __half2 h0 = __float22half2_rn(make_float2(v.x, v.y));
        __half2 h1 = __float22half2_rn(make_float2(v.z, v.w));
        uint2 p; p.x = *(uint32_t*)&h0; p.y = *(uint32_t*)&h1;
        xo[c] = p;
#pragma unroll
        for (int e = 0; e < NEXP; e++) {
            float4 w = s_wg[e * 256 + c];
            acc[e] += v.x * w.x + v.y * w.y + v.z * w.z + v.w * w.w;
        }
    }
#pragma unroll
    for (int e = 0; e < NEXP; e++) {
#pragma unroll
        for (int o = 16; o > 0; o >>= 1)
            acc[e] += __shfl_xor_sync(0xFFFFFFFFu, acc[e], o);
    }

    if (lid == 0) {
        float l[NEXP];
#pragma unroll
        for (int e = 0; e < NEXP; e++) l[e] = acc[e] + bg[e];  // TEMP = 1
        int i0 = 0;
#pragma unroll
        for (int e = 1; e < NEXP; e++) if (l[e] > l[i0]) i0 = e;
        int i1 = -1;
#pragma unroll
        for (int e = 0; e < NEXP; e++) {
            if (e == i0) continue;
            if (i1 < 0 || l[e] > l[i1]) i1 = e;
        }
        float mx = l[0];
#pragma unroll
        for (int e = 1; e < NEXP; e++) mx = fmaxf(mx, l[e]);
        float s = 0.f;
#pragma unroll
        for (int e = 0; e < NEXP; e++) s += expf(l[e] - mx);
        float inv = 1.f / s;
        float w0 = expf(l[i0] - mx) * inv;
        float w1 = expf(l[i1] - mx) * inv;
        int p0 = atomicAdd(&g_cnt[i0], 1);
        g_tok[i0 * T_TOKENS + p0] = t; g_wt[i0 * T_TOKENS + p0] = w0;
        int p1 = atomicAdd(&g_cnt[i1], 1);
        g_tok[i1 * T_TOKENS + p1] = t; g_wt[i1 * T_TOKENS + p1] = w1;
    }
}

// ---------------------------------------------------------------------------
// sm_100-portable helpers
// ---------------------------------------------------------------------------
__device__ __forceinline__ uint32_t smem_u32(const void* p) {
    uint32_t a;
    asm("{ .reg .u64 t; cvta.to.shared.u64 t, %1; cvt.u32.u64 %0, t; }"
        : "=r"(a) : "l"(p));
    return a;
}
__device__ __forceinline__ void cp16(uint32_t dst, const void* src, uint32_t sz) {
    asm volatile("cp.async.cg.shared.global [%0], [%1], 16, %2;"
                 :: "r"(dst), "l"(src), "r"(sz) : "memory");
}
__device__ __forceinline__ void ldm_x4(uint32_t* r, uint32_t addr) {
    asm volatile("ldmatrix.sync.aligned.m8n8.x4.shared.b16 {%0,%1,%2,%3}, [%4];"
                 : "=r"(r[0]), "=r"(r[1]), "=r"(r[2]), "=r"(r[3]) : "r"(addr));
}
__device__ __forceinline__ void mma_f16(float* c, const uint32_t* a,
                                        uint32_t b0, uint32_t b1) {
    asm volatile(
        "mma.sync.aligned.m16n8k16.row.col.f32.f16.f16.f32 "
        "{%0,%1,%2,%3}, {%4,%5,%6,%7}, {%8,%9}, {%0,%1,%2,%3};"
        : "+f"(c[0]), "+f"(c[1]), "+f"(c[2]), "+f"(c[3])
        : "r"(a[0]), "r"(a[1]), "r"(a[2]), "r"(a[3]), "r"(b0), "r"(b1));
}
__device__ __forceinline__ void red2(float* p, float a, float b) {
    asm volatile("red.relaxed.gpu.global.add.v2.f32 [%0], {%1, %2};"
                 :: "l"(p), "f"(a), "f"(b) : "memory");
}

// ---------------------------------------------------------------------------
// Kernel 2: routed GEMM. grid = (4 N-tiles, 64 M-tiles, 8 experts).
// 128x256x1024 per CTA; BK=32; 8 warps of 64x64; pitch 80 B (conflict-free
// ldmatrix); reg fragment double-buffer across kk and stage boundary.
// 4 smem buffers, lookahead 2, prefetch issued BEFORE wait_group so the
// cp.async issue fills the wait stall. Safety: prefetch(s+2) writes buf
// (s+2)%4, last read at stage s-2; the bar in iteration s-1 (passed by all
// warps before any warp reaches iteration s) ordered all compute(s-2) first.
//   per stage: prefetch(s+2); commit; wait_group(2); bar;
//              ldsm kk0(s); mma kk1(s-1); ldsm kk1(s); mma kk0(s)
// SMEM: 4*10240 + 4*20480 + 1024 = 123904 B (1 CTA/SM).
// ---------------------------------------------------------------------------
#define PITCH_B  80       // bytes per smem row
#define STG_A    10240    // 128 rows * 80 B
#define STG_B    20480    // 256 rows * 80 B
#define NBUF     4

__global__ void __launch_bounds__(256, 1)
moe_gemm_kernel(const float* __restrict__ bias, float* __restrict__ out) {
    extern __shared__ char smem[];
    const int e  = blockIdx.z;
    const int mt = blockIdx.y;
    const int nt = blockIdx.x;
    const int cnt = g_cnt[e];
    if (mt * 128 >= cnt) return;

    const int tid  = threadIdx.x;
    const int wid  = tid >> 5;
    const int lane = tid & 31;
    const int wm   = wid & 1;   // 2 m-blocks of 64
    const int wn   = wid >> 1;  // 4 n-blocks of 64

    char* sA = smem;
    char* sB = smem + NBUF * STG_A;
    int*   sTok = (int*)(smem + NBUF * (STG_A + STG_B));
    float* sWt  = (float*)(smem + NBUF * (STG_A + STG_B) + 512);

    if (tid < 128) {
        int idx = mt * 128 + tid;
        int tok = -1; float w = 0.f;
        if (idx < cnt) { tok = g_tok[e * T_TOKENS + idx]; w = g_wt[e * T_TOKENS + idx]; }
        sTok[tid] = tok; sWt[tid] = w;
    }
    __syncthreads();

    // --- cp.async slots. A: 512 chunks (2/thread); B: 1024 chunks (4/thread)
    const __half* aSrc[2];
    uint32_t      aSz[2];
    uint32_t      aOff[2];
    const __half* bSrc[4];
    uint32_t      bOff[4];
    const __half* wrow = g_w_h + ((size_t)(e * OUTD + nt * 256)) * DIM;
#pragma unroll
    for (int i = 0; i < 2; i++) {
        int f = tid + i * 256;
        int r = f >> 2, q = f & 3;   // A row, 16B chunk
        int tok = sTok[r];
        aSrc[i] = (tok >= 0 ? g_x_h + (size_t)tok * DIM : g_x_h) + q * 8;
        aSz[i]  = (tok >= 0) ? 16u : 0u;   // zfill padding rows
        aOff[i] = (uint32_t)(r * PITCH_B + q * 16);
    }
#pragma unroll
    for (int i = 0; i < 4; i++) {
        int f = tid + i * 256;
        int r = f >> 2, q = f & 3;   // B row (0..255), 16B chunk
        bSrc[i] = wrow + (size_t)r * DIM + q * 8;
        bOff[i] = (uint32_t)(r * PITCH_B + q * 16);
    }

    const uint32_t aBase = smem_u32(sA);
    const uint32_t bBase = smem_u32(sB);

    auto prefetch = [&](int s, int buf) {
        uint32_t sta = (uint32_t)buf * STG_A;
        uint32_t stb = (uint32_t)buf * STG_B;
        int ko = s * 32;  // half offset along K
#pragma unroll
        for (int i = 0; i < 2; i++) cp16(aBase + sta + aOff[i], aSrc[i] + ko, aSz[i]);
#pragma unroll
        for (int i = 0; i < 4; i++) cp16(bBase + stb + bOff[i], bSrc[i] + ko, 16u);
    };

    prefetch(0, 0);
    asm volatile("cp.async.commit_group;" ::: "memory");
    prefetch(1, 1);
    asm volatile("cp.async.commit_group;" ::: "memory");

    // ldmatrix fragment base addresses (per-buffer offsets added in loop)
    const uint32_t aA0 = aBase + (uint32_t)((wm * 64 + (lane & 15)) * PITCH_B)
                               + (uint32_t)((lane >> 4) * 16);
    const uint32_t bA0 = bBase + (uint32_t)((wn * 64 + ((lane >> 4) << 3) + (lane & 7)) * PITCH_B)
                               + (uint32_t)(((lane >> 3) & 1) * 16);

    float c[4][8][4];
#pragma unroll
    for (int mf = 0; mf < 4; mf++)
#pragma unroll
        for (int nf = 0; nf < 8; nf++)
#pragma unroll
            for (int j = 0; j < 4; j++) c[mf][nf][j] = 0.f;

    uint32_t af[2][4][4];   // [kk-slot][mf][reg]
    uint32_t bf[2][4][4];   // [kk-slot][pr][reg]

    auto ldsFrag = [&](int slot, uint32_t sa, uint32_t sb, int kk) {
#pragma unroll
        for (int mf = 0; mf < 4; mf++)
            ldm_x4(af[slot][mf], sa + (uint32_t)(mf * 16 * PITCH_B) + (uint32_t)(kk * 32));
#pragma unroll
        for (int pr = 0; pr < 4; pr++)
            ldm_x4(bf[slot][pr], sb + (uint32_t)(pr * 16 * PITCH_B) + (uint32_t)(kk * 32));
    };
    auto mmaBlk = [&](int slot) {
#pragma unroll
        for (int mf = 0; mf < 4; mf++)
#pragma unroll
            for (int nf = 0; nf < 8; nf++)
                mma_f16(c[mf][nf], af[slot][mf],
                        bf[slot][nf >> 1][(nf & 1) * 2], bf[slot][nf >> 1][(nf & 1) * 2 + 1]);
    };

    // ---- peeled stage 0: prefetch BEFORE wait (fills the stall) ----
    prefetch(2, 2);
    asm volatile("cp.async.commit_group;" ::: "memory");
    asm volatile("cp.async.wait_group 2;" ::: "memory");   // stage 0 landed
    __syncthreads();
    ldsFrag(0, aA0, bA0, 0);
    ldsFrag(1, aA0, bA0, 1);
    mmaBlk(0);

    for (int s = 1; s < 32; s++) {
        // Issue next loads first; commit every iter (empty groups near tail
        // keep the wait_group count aligned).
        if (s + 2 < 32) prefetch(s + 2, (s + 2) % NBUF);
        asm volatile("cp.async.commit_group;" ::: "memory");
        asm volatile("cp.async.wait_group 2;" ::: "memory");  // stage s landed
        __syncthreads();  // publish stage s; all warps past compute(s-1)

        const uint32_t off = (uint32_t)(s % NBUF);
        const uint32_t sa = aA0 + off * STG_A;
        const uint32_t sb = bA0 + off * STG_B;
        ldsFrag(0, sa, sb, 0);   // stage s, kk0
        mmaBlk(1);               // stage s-1, kk1 (regs only)
        ldsFrag(1, sa, sb, 1);   // stage s, kk1
        mmaBlk(0);               // stage s, kk0
    }
    mmaBlk(1);  // final stage kk1

    // --- epilogue: bias + gate-weight scale + vectorized global reduction ---
    const int nbase = nt * 256;
    const float* bptr = bias + e * OUTD + nbase;
#pragma unroll
    for (int mf = 0; mf < 4; mf++) {
        int m0 = wm * 64 + mf * 16 + (lane >> 2);
        int m1 = m0 + 8;
        int t0 = sTok[m0], t1 = sTok[m1];
        float w0 = sWt[m0], w1 = sWt[m1];
#pragma unroll
        for (int nf = 0; nf < 8; nf++) {
            int col = wn * 64 + nf * 8 + 2 * (lane & 3);
            float2 bb = *(const float2*)(bptr + col);
            if (t0 >= 0) {
                red2(out + (size_t)t0 * OUTD + nbase + col,
                     w0 * (c[mf][nf][0] + bb.x), w0 * (c[mf][nf][1] + bb.y));
            }
            if (t1 >= 0) {
                red2(out + (size_t)t1 * OUTD + nbase + col,
                     w1 * (c[mf][nf][2] + bb.x), w1 * (c[mf][nf][3] + bb.y));
            }
        }
    }
}

// ---------------------------------------------------------------------------
extern "C" void kernel_launch(void* const* d_in, const int* in_sizes, int n_in,
                              void* d_out, int out_size) {
    const float* x  = (const float*)d_in[0];   // [4,2048,1024]
    const float* W  = (const float*)d_in[1];   // [8,1024,1024]
    const float* b  = (const float*)d_in[2];   // [8,1024]
    const float* Wg = (const float*)d_in[3];   // [8,1024]
    const float* bg = (const float*)d_in[4];   // [8]
    float* out = (float*)d_out;                // [4,2048,1024] f32

    static void* cnt_addr = nullptr;
    if (!cnt_addr) {
        cudaGetSymbolAddress(&cnt_addr, g_cnt);
        cudaFuncSetAttribute(moe_gemm_kernel,
                             cudaFuncAttributeMaxDynamicSharedMemorySize, 123904);
    }

    cudaMemsetAsync(cnt_addr, 0, NEXP * sizeof(int));
    fused_prep_gating<<<3072, 256>>>(x, (const float4*)W, Wg, bg, (float4*)out);
    dim3 grid(4, 64, 8);
    moe_gemm_kernel<<<grid, 256, 123904>>>(b, out);
}

// round 14
// speedup vs baseline: 1.1363x; 1.0190x over previous
#include <cuda_runtime.h>
#include <cuda_fp16.h>
#include <cstdint>

// ---------------------------------------------------------------------------
// MoE top-2 projection: out[t] = sum_k w_k * (x[t] @ W[e_k]^T + b[e_k])
// x:[8192,1024] f32, W:[8,1024,1024], b:[8,1024], Wg:[8,1024], bg:[8]
// Route -> per-expert gathered GEMM with mma.sync fp16 (f32 accumulate).
// Base = R9 exact (best measured: 162.7 total / 134.6 GEMM). ONE delta:
// the two warps sharing each SMSP (wid, wid+4) run mirrored kk schedules
// so their ldsm and mma bursts interleave instead of colliding in lockstep.
// ---------------------------------------------------------------------------

#define T_TOKENS 8192
#define DIM      1024
#define OUTD     1024
#define NEXP     8

// Scratch (allocation-free rule: __device__ globals)
__device__ __half g_x_h[T_TOKENS * DIM];          // 16 MB
__device__ __half g_w_h[NEXP * OUTD * DIM];       // 16 MB
__device__ int    g_cnt[NEXP];                    // zeroed via cudaMemsetAsync
__device__ int    g_tok[NEXP * T_TOKENS];
__device__ float  g_wt [NEXP * T_TOKENS];

// ---------------------------------------------------------------------------
// Kernel 1 (fused): blocks [0,1024) = gating + x->fp16; blocks [1024,3072) =
// W->fp16 conversion + zero-init of d_out. (Byte-identical to R9.)
// ---------------------------------------------------------------------------
__global__ void __launch_bounds__(256)
fused_prep_gating(const float* __restrict__ x,
                  const float4* __restrict__ W,
                  const float* __restrict__ wg,
                  const float* __restrict__ bg,
                  float4* __restrict__ out4) {
    __shared__ float4 s_wg[NEXP * DIM / 4];  // 32 KB (gating blocks only)
    const int tid = threadIdx.x;

    if (blockIdx.x >= 1024) {
        // ---- prep part: W fp16 convert + out zero ----
        const int gid = (blockIdx.x - 1024) * 256 + tid;
        const int stride = 2048 * 256;        // 524288
        uint4* wh = reinterpret_cast<uint4*>(g_w_h);
        float4 v[4];
#pragma unroll
        for (int i = 0; i < 2; i++) {
            int j = gid + i * stride;
            v[2 * i]     = W[2 * j];
            v[2 * i + 1] = W[2 * j + 1];
        }
#pragma unroll
        for (int i = 0; i < 2; i++) {
            int j = gid + i * stride;
            __half2 h0 = __float22half2_rn(make_float2(v[2*i].x,   v[2*i].y));
            __half2 h1 = __float22half2_rn(make_float2(v[2*i].z,   v[2*i].w));
            __half2 h2 = __float22half2_rn(make_float2(v[2*i+1].x, v[2*i+1].y));
            __half2 h3 = __float22half2_rn(make_float2(v[2*i+1].z, v[2*i+1].w));
            uint4 p;
            p.x = *(uint32_t*)&h0; p.y = *(uint32_t*)&h1;
            p.z = *(uint32_t*)&h2; p.w = *(uint32_t*)&h3;
            wh[j] = p;
        }
        float4 z = make_float4(0.f, 0.f, 0.f, 0.f);
#pragma unroll
        for (int i = 0; i < 4; i++) out4[gid + i * stride] = z;
        return;
    }

    // ---- gating part: exact fp32 gate, top-2 route, x -> fp16 ----
    const float4* wg4 = (const float4*)wg;
    for (int i = tid; i < NEXP * DIM / 4; i += 256) s_wg[i] = wg4[i];
    __syncthreads();

    const int lid = tid & 31;
    const int t = blockIdx.x * 8 + (tid >> 5);
    const float4* xr = (const float4*)(x + (size_t)t * DIM);
    uint2* xo = (uint2*)(g_x_h + (size_t)t * DIM);

    float acc[NEXP];
#pragma unroll
    for (int e = 0; e < NEXP; e++) acc[e] = 0.f;

#pragma unroll
    for (int j = 0; j < 8; j++) {
        int c = lid + j * 32;
        float4 v = xr[c];
        __half2 h0 = __float22half2_rn(make_float2(v.x, v.y));
        __half2 h1 = __float22half2_rn(make_float2(v.z, v.w));
        uint2 p; p.x = *(uint32_t*)&h0; p.y = *(uint32_t*)&h1;
        xo[c] = p;
#pragma unroll
        for (int e = 0; e < NEXP; e++) {
            float4 w = s_wg[e * 256 + c];
            acc[e] += v.x * w.x + v.y * w.y + v.z * w.z + v.w * w.w;
        }
    }
#pragma unroll
    for (int e = 0; e < NEXP; e++) {
#pragma unroll
        for (int o = 16; o > 0; o >>= 1)
            acc[e] += __shfl_xor_sync(0xFFFFFFFFu, acc[e], o);
    }

    if (lid == 0) {
        float l[NEXP];
#pragma unroll
        for (int e = 0; e < NEXP; e++) l[e] = acc[e] + bg[e];  // TEMP = 1
        int i0 = 0;
#pragma unroll
        for (int e = 1; e < NEXP; e++) if (l[e] > l[i0]) i0 = e;
        int i1 = -1;
#pragma unroll
        for (int e = 0; e < NEXP; e++) {
            if (e == i0) continue;
            if (i1 < 0 || l[e] > l[i1]) i1 = e;
        }
        float mx = l[0];
#pragma unroll
        for (int e = 1; e < NEXP; e++) mx = fmaxf(mx, l[e]);
        float s = 0.f;
#pragma unroll
        for (int e = 0; e < NEXP; e++) s += expf(l[e] - mx);
        float inv = 1.f / s;
        float w0 = expf(l[i0] - mx) * inv;
        float w1 = expf(l[i1] - mx) * inv;
        int p0 = atomicAdd(&g_cnt[i0], 1);
        g_tok[i0 * T_TOKENS + p0] = t; g_wt[i0 * T_TOKENS + p0] = w0;
        int p1 = atomicAdd(&g_cnt[i1], 1);
        g_tok[i1 * T_TOKENS + p1] = t; g_wt[i1 * T_TOKENS + p1] = w1;
    }
}

// ---------------------------------------------------------------------------
// sm_100-portable helpers
// ---------------------------------------------------------------------------
__device__ __forceinline__ uint32_t smem_u32(const void* p) {
    uint32_t a;
    asm("{ .reg .u64 t; cvta.to.shared.u64 t, %1; cvt.u32.u64 %0, t; }"
        : "=r"(a) : "l"(p));
    return a;
}
__device__ __forceinline__ void cp16(uint32_t dst, const void* src, uint32_t sz) {
    asm volatile("cp.async.cg.shared.global [%0], [%1], 16, %2;"
                 :: "r"(dst), "l"(src), "r"(sz) : "memory");
}
__device__ __forceinline__ void ldm_x4(uint32_t* r, uint32_t addr) {
    asm volatile("ldmatrix.sync.aligned.m8n8.x4.shared.b16 {%0,%1,%2,%3}, [%4];"
                 : "=r"(r[0]), "=r"(r[1]), "=r"(r[2]), "=r"(r[3]) : "r"(addr));
}
__device__ __forceinline__ void mma_f16(float* c, const uint32_t* a,
                                        uint32_t b0, uint32_t b1) {
    asm volatile(
        "mma.sync.aligned.m16n8k16.row.col.f32.f16.f16.f32 "
        "{%0,%1,%2,%3}, {%4,%5,%6,%7}, {%8,%9}, {%0,%1,%2,%3};"
        : "+f"(c[0]), "+f"(c[1]), "+f"(c[2]), "+f"(c[3])
        : "r"(a[0]), "r"(a[1]), "r"(a[2]), "r"(a[3]), "r"(b0), "r"(b1));
}
__device__ __forceinline__ void red2(float* p, float a, float b) {
    asm volatile("red.relaxed.gpu.global.add.v2.f32 [%0], {%1, %2};"
                 :: "l"(p), "f"(a), "f"(b) : "memory");
}

// ---------------------------------------------------------------------------
// Kernel 2: routed GEMM. grid = (4 N-tiles, 64 M-tiles, 8 experts).
// 128x256x1024 per CTA; BK=32; 8 warps of 64x64; pitch 80 B (conflict-free
// ldmatrix); 3 smem buffers, lookahead 2, wait_group 1, one bar per stage
// (exact R9 pipeline). DELTA: SMSP phase stagger — warps 0-3 run the kk0-led
// schedule, warps 4-7 the kk1-led mirror, so the two warps sharing each SMSP
// interleave ldsm and mma bursts instead of stalling in lockstep.
//   phase0 stage s: lds(0,kk0); mma(1)[s-1,kk1]; lds(1,kk1); mma(0)[s,kk0]
//   phase1 stage s: lds(1,kk1); mma(0)[s-1,kk0]; lds(0,kk0); mma(1)[s,kk1]
// Both orders read buffer s within its valid window and cover every
// (stage, kk) exactly once (peel: phase0 seeds kk0+kk1 & mma kk0; phase1
// seeds kk1+kk0 & mma kk1; drain: mma the leftover slot).
// SMEM: 3*10240 + 3*20480 + 1024 = 93184 B (1 CTA/SM).
// ---------------------------------------------------------------------------
#define PITCH_B  80       // bytes per smem row
#define STG_A    10240    // 128 rows * 80 B
#define STG_B    20480    // 256 rows * 80 B

__global__ void __launch_bounds__(256, 1)
moe_gemm_kernel(const float* __restrict__ bias, float* __restrict__ out) {
    extern __shared__ char smem[];
    const int e  = blockIdx.z;
    const int mt = blockIdx.y;
    const int nt = blockIdx.x;
    const int cnt = g_cnt[e];
    if (mt * 128 >= cnt) return;

    const int tid  = threadIdx.x;
    const int wid  = tid >> 5;
    const int lane = tid & 31;
    const int wm   = wid & 1;        // 2 m-blocks of 64
    const int wn   = wid >> 1;       // 4 n-blocks of 64
    const int ph   = (wid >> 2) & 1; // SMSP phase: warps 0-3 -> 0, 4-7 -> 1

    char* sA = smem;
    char* sB = smem + 3 * STG_A;
    int*   sTok = (int*)(smem + 3 * STG_A + 3 * STG_B);
    float* sWt  = (float*)(smem + 3 * STG_A + 3 * STG_B + 512);

    if (tid < 128) {
        int idx = mt * 128 + tid;
        int tok = -1; float w = 0.f;
        if (idx < cnt) { tok = g_tok[e * T_TOKENS + idx]; w = g_wt[e * T_TOKENS + idx]; }
        sTok[tid] = tok; sWt[tid] = w;
    }
    __syncthreads();

    // --- cp.async slots. A: 512 chunks (2/thread); B: 1024 chunks (4/thread)
    const __half* aSrc[2];
    uint32_t      aSz[2];
    uint32_t      aOff[2];
    const __half* bSrc[4];
    uint32_t      bOff[4];
    const __half* wrow = g_w_h + ((size_t)(e * OUTD + nt * 256)) * DIM;
#pragma unroll
    for (int i = 0; i < 2; i++) {
        int f = tid + i * 256;
        int r = f >> 2, q = f & 3;   // A row, 16B chunk
        int tok = sTok[r];
        aSrc[i] = (tok >= 0 ? g_x_h + (size_t)tok * DIM : g_x_h) + q * 8;
        aSz[i]  = (tok >= 0) ? 16u : 0u;   // zfill padding rows
        aOff[i] = (uint32_t)(r * PITCH_B + q * 16);
    }
#pragma unroll
    for (int i = 0; i < 4; i++) {
        int f = tid + i * 256;
        int r = f >> 2, q = f & 3;   // B row (0..255), 16B chunk
        bSrc[i] = wrow + (size_t)r * DIM + q * 8;
        bOff[i] = (uint32_t)(r * PITCH_B + q * 16);
    }

    const uint32_t aBase = smem_u32(sA);
    const uint32_t bBase = smem_u32(sB);

    auto prefetch = [&](int s, int buf) {
        uint32_t sta = (uint32_t)buf * STG_A;
        uint32_t stb = (uint32_t)buf * STG_B;
        int ko = s * 32;  // half offset along K
#pragma unroll
        for (int i = 0; i < 2; i++) cp16(aBase + sta + aOff[i], aSrc[i] + ko, aSz[i]);
#pragma unroll
        for (int i = 0; i < 4; i++) cp16(bBase + stb + bOff[i], bSrc[i] + ko, 16u);
    };

    prefetch(0, 0);
    asm volatile("cp.async.commit_group;" ::: "memory");
    prefetch(1, 1);
    asm volatile("cp.async.commit_group;" ::: "memory");

    // ldmatrix fragment base addresses (per-buffer offsets added in loop)
    const uint32_t aA0 = aBase + (uint32_t)((wm * 64 + (lane & 15)) * PITCH_B)
                               + (uint32_t)((lane >> 4) * 16);
    const uint32_t bA0 = bBase + (uint32_t)((wn * 64 + ((lane >> 4) << 3) + (lane & 7)) * PITCH_B)
                               + (uint32_t)(((lane >> 3) & 1) * 16);

    float c[4][8][4];
#pragma unroll
    for (int mf = 0; mf < 4; mf++)
#pragma unroll
        for (int nf = 0; nf < 8; nf++)
#pragma unroll
            for (int j = 0; j < 4; j++) c[mf][nf][j] = 0.f;

    uint32_t af[2][4][4];   // [kk-slot][mf][reg]
    uint32_t bf[2][4][4];   // [kk-slot][pr][reg]

    auto ldsFrag = [&](int slot, uint32_t sa, uint32_t sb, int kk) {
#pragma unroll
        for (int mf = 0; mf < 4; mf++)
            ldm_x4(af[slot][mf], sa + (uint32_t)(mf * 16 * PITCH_B) + (uint32_t)(kk * 32));
#pragma unroll
        for (int pr = 0; pr < 4; pr++)
            ldm_x4(bf[slot][pr], sb + (uint32_t)(pr * 16 * PITCH_B) + (uint32_t)(kk * 32));
    };
    auto mmaBlk = [&](int slot) {
#pragma unroll
        for (int mf = 0; mf < 4; mf++)
#pragma unroll
            for (int nf = 0; nf < 8; nf++)
                mma_f16(c[mf][nf], af[slot][mf],
                        bf[slot][nf >> 1][(nf & 1) * 2], bf[slot][nf >> 1][(nf & 1) * 2 + 1]);
    };

    // Phase-dependent slot/kk mapping: lead = slot computed in-stage,
    // trail = slot carried from previous stage.
    const int lead  = ph;        // phase0: slot0<-kk0 ; phase1: slot1<-kk1
    const int trail = ph ^ 1;
    const int kkLead  = ph;      // phase0 leads with kk0, phase1 with kk1
    const int kkTrail = ph ^ 1;

    // ---- peeled stage 0 ----
    asm volatile("cp.async.wait_group 1;" ::: "memory");
    __syncthreads();
    prefetch(2, 2);
    asm volatile("cp.async.commit_group;" ::: "memory");
    ldsFrag(lead,  aA0, bA0, kkLead);
    ldsFrag(trail, aA0, bA0, kkTrail);
    mmaBlk(lead);                // stage 0, kkLead

    for (int s = 1; s < 32; s++) {
        asm volatile("cp.async.wait_group 1;" ::: "memory");
        __syncthreads();  // stage s smem ready; buffer (s-1)%3 fully read
        if (s + 2 < 32) prefetch(s + 2, (s + 2) % 3);
        asm volatile("cp.async.commit_group;" ::: "memory");

        const uint32_t off = (uint32_t)(s % 3);
        const uint32_t sa = aA0 + off * STG_A;
        const uint32_t sb = bA0 + off * STG_B;
        ldsFrag(lead, sa, sb, kkLead);   // stage s, lead kk
        mmaBlk(trail);                   // stage s-1, trail kk (regs only)
        ldsFrag(trail, sa, sb, kkTrail); // stage s, trail kk
        mmaBlk(lead);                    // stage s, lead kk
    }
    mmaBlk(trail);  // final stage, trail kk

    // --- epilogue: bias + gate-weight scale + vectorized global reduction ---
    const int nbase = nt * 256;
    const float* bptr = bias + e * OUTD + nbase;
#pragma unroll
    for (int mf = 0; mf < 4; mf++) {
        int m0 = wm * 64 + mf * 16 + (lane >> 2);
        int m1 = m0 + 8;
        int t0 = sTok[m0], t1 = sTok[m1];
        float w0 = sWt[m0], w1 = sWt[m1];
#pragma unroll
        for (int nf = 0; nf < 8; nf++) {
            int col = wn * 64 + nf * 8 + 2 * (lane & 3);
            float2 bb = *(const float2*)(bptr + col);
            if (t0 >= 0) {
                red2(out + (size_t)t0 * OUTD + nbase + col,
                     w0 * (c[mf][nf][0] + bb.x), w0 * (c[mf][nf][1] + bb.y));
            }
            if (t1 >= 0) {
                red2(out + (size_t)t1 * OUTD + nbase + col,
                     w1 * (c[mf][nf][2] + bb.x), w1 * (c[mf][nf][3] + bb.y));
            }
        }
    }
}

// ---------------------------------------------------------------------------
extern "C" void kernel_launch(void* const* d_in, const int* in_sizes, int n_in,
                              void* d_out, int out_size) {
    const float* x  = (const float*)d_in[0];   // [4,2048,1024]
    const float* W  = (const float*)d_in[1];   // [8,1024,1024]
    const float* b  = (const float*)d_in[2];   // [8,1024]
    const float* Wg = (const float*)d_in[3];   // [8,1024]
    const float* bg = (const float*)d_in[4];   // [8]
    float* out = (float*)d_out;                // [4,2048,1024] f32

    static void* cnt_addr = nullptr;
    if (!cnt_addr) {
        cudaGetSymbolAddress(&cnt_addr, g_cnt);
        cudaFuncSetAttribute(moe_gemm_kernel,
                             cudaFuncAttributeMaxDynamicSharedMemorySize, 93184);
    }

    cudaMemsetAsync(cnt_addr, 0, NEXP * sizeof(int));
    fused_prep_gating<<<3072, 256>>>(x, (const float4*)W, Wg, bg, (float4*)out);
    dim3 grid(4, 64, 8);
    moe_gemm_kernel<<<grid, 256, 93184>>>(b, out);
}